// round 6
// baseline (speedup 1.0000x reference)
#include <cuda_runtime.h>
#include <cuda_bf16.h>

// Problem shape (fixed by dataset):
//   S = 8192  source codes
//   G = 1024  groups
//   T = 4096  time segments (t0 sorted ascending)
//   E = 16384 events
//
// out[t, g] = sum over events e with start[e] <= t0[t] < end[e] of
//             rate[e] * weights[index[e]], grouped by group_id[index[e]].
//
// Each event covers a contiguous time range [lo, hi) (t0 sorted) -> it is
// exactly two difference-array endpoints: +w at row lo, -w at row hi.
// Instead of materializing the 16MB diff array in gmem, we bucket the 32K
// endpoint records by 8-row time chunk, accumulate per-chunk column sums
// with atomics, scan those, and reconstruct each chunk's diff tile in
// SHARED memory inside the final apply kernel. Only large gmem op left is
// the 16MB output write.

#define T_DIM 4096
#define G_DIM 1024
#define G4    (G_DIM / 4)     // 256 float4 columns
#define CH    8               // rows per chunk
#define NCH   (T_DIM / CH)    // 512 chunks
#define CAP   512             // record capacity per chunk (peak ~100, sigma~10)

// Per-chunk endpoint records: x = (row_in_chunk<<10)|group, y = float bits of w
__device__ int    g_cnt[NCH];
__device__ uint2  g_rec[NCH][CAP];          // 2 MB
// Per-chunk column sums, column-major [j][c] so the scan kernel is coalesced.
__device__ float4 g_part[G4][NCH];          // 2 MB

// ---------------------------------------------------------------------------
// Kernel 0: zero the scratch (counts + partials)
// ---------------------------------------------------------------------------
__global__ void __launch_bounds__(256)
zero_kernel()
{
    int idx = blockIdx.x * 256 + threadIdx.x;           // grid 512 -> 131072
    ((float4*)g_part)[idx] = make_float4(0.f, 0.f, 0.f, 0.f);
    if (idx < NCH) g_cnt[idx] = 0;
}

// ---------------------------------------------------------------------------
// Kernel 1: per-event binary search -> two endpoint records + partial sums
// ---------------------------------------------------------------------------
__device__ __forceinline__ void push_record(int row, int g, float w)
{
    int chunk = row >> 3;                 // CH = 8
    int r     = row & (CH - 1);
    int pos = atomicAdd(&g_cnt[chunk], 1);
    if (pos < CAP) {
        g_rec[chunk][pos] = make_uint2((unsigned)((r << 10) | g),
                                       __float_as_uint(w));
        // chunk column-sum contribution (same delta), kept consistent
        atomicAdd(&((float*)&g_part[g >> 2][chunk])[g & 3], w);
    }
}

__global__ void bucket_kernel(const int* __restrict__ index,
                              const float* __restrict__ rate,
                              const float* __restrict__ starttime,
                              const float* __restrict__ endtime,
                              const float* __restrict__ t0,
                              const int* __restrict__ group_id,
                              const float* __restrict__ weights,
                              int E)
{
    __shared__ float sh_t0[T_DIM];
    for (int i = threadIdx.x; i < T_DIM; i += blockDim.x)
        sh_t0[i] = t0[i];
    __syncthreads();

    int e = blockIdx.x * blockDim.x + threadIdx.x;
    if (e >= E) return;

    float st = starttime[e];
    float en = endtime[e];

    // lower_bound: first idx with t0[idx] >= x  (matches start <= t0 < end)
    int lo = 0, hi = T_DIM;
    while (lo < hi) {
        int m = (lo + hi) >> 1;
        if (sh_t0[m] < st) lo = m + 1; else hi = m;
    }
    int lo2 = lo, hi2 = T_DIM;
    while (lo2 < hi2) {
        int m = (lo2 + hi2) >> 1;
        if (sh_t0[m] < en) lo2 = m + 1; else hi2 = m;
    }
    if (lo >= lo2) return;                 // no active segment

    int src = index[e];
    float w = rate[e] * weights[src];
    int g = group_id[src];

    push_record(lo, g, w);
    if (lo2 < T_DIM) push_record(lo2, g, -w);
}

// ---------------------------------------------------------------------------
// Kernel 2: per-column exclusive scan of the NCH chunk sums (Hillis-Steele).
// Block = one float4 column; reads/writes are fully coalesced ([j][c] layout).
// ---------------------------------------------------------------------------
__global__ void __launch_bounds__(NCH)
scan_partials_kernel()
{
    __shared__ float4 sh[NCH];            // 8 KB
    int j = blockIdx.x;
    int c = threadIdx.x;

    float4 v = g_part[j][c];
    sh[c] = v;
    __syncthreads();

    #pragma unroll
    for (int off = 1; off < NCH; off <<= 1) {
        float4 add = make_float4(0.f, 0.f, 0.f, 0.f);
        if (c >= off) add = sh[c - off];
        __syncthreads();
        sh[c].x += add.x; sh[c].y += add.y; sh[c].z += add.z; sh[c].w += add.w;
        __syncthreads();
    }

    float4 inc = sh[c];
    g_part[j][c] = make_float4(inc.x - v.x, inc.y - v.y,
                               inc.z - v.z, inc.w - v.w);   // exclusive
}

// ---------------------------------------------------------------------------
// Kernel 3: apply. Rebuild the chunk's 8x1024 diff tile in shared memory
// from its bucketed records, prefix within the chunk seeded by the scanned
// offset, write the output tile. Only reads scratch; writes 32KB of output.
// ---------------------------------------------------------------------------
__global__ void __launch_bounds__(256)
apply_kernel(float4* __restrict__ out)
{
    __shared__ float4 sh[CH][G4];         // 32 KB
    int c = blockIdx.x;                   // chunk 0..511
    int t = threadIdx.x;                  // float4 column 0..255

    // zero the tile
    #pragma unroll
    for (int i = 0; i < CH; i++)
        sh[i][t] = make_float4(0.f, 0.f, 0.f, 0.f);
    __syncthreads();

    // scatter this chunk's endpoint records (shared atomics, ~100 records)
    int n = g_cnt[c];
    if (n > CAP) n = CAP;
    float* shf = (float*)sh;
    for (int i = t; i < n; i += 256) {
        uint2 rec = g_rec[c][i];
        int r = rec.x >> 10;
        int g = rec.x & 1023;
        atomicAdd(&shf[r * G_DIM + g], __uint_as_float(rec.y));
    }
    __syncthreads();

    // within-chunk inclusive prefix, seeded by exclusive chunk offset
    float4 run = g_part[t][c];
    float4* p = out + (size_t)c * CH * G4 + t;
    #pragma unroll
    for (int r = 0; r < CH; r++) {
        float4 v = sh[r][t];
        run.x += v.x; run.y += v.y; run.z += v.z; run.w += v.w;
        p[r * G4] = run;
    }
}

// ---------------------------------------------------------------------------
extern "C" void kernel_launch(void* const* d_in, const int* in_sizes, int n_in,
                              void* d_out, int out_size)
{
    const int*   index     = (const int*)  d_in[0];
    const float* rate      = (const float*)d_in[1];
    const float* starttime = (const float*)d_in[2];
    const float* endtime   = (const float*)d_in[3];
    const float* t0        = (const float*)d_in[4];
    const int*   group_id  = (const int*)  d_in[5];
    const float* weights   = (const float*)d_in[6];
    float*       out       = (float*)d_out;

    int E = in_sizes[0];

    zero_kernel<<<(G4 * NCH) / 256, 256>>>();

    int threads = 256;
    int blocks  = (E + threads - 1) / threads;
    bucket_kernel<<<blocks, threads>>>(index, rate, starttime, endtime,
                                       t0, group_id, weights, E);

    scan_partials_kernel<<<G4, NCH>>>();

    apply_kernel<<<NCH, 256>>>((float4*)out);
}

// round 7
// speedup vs baseline: 1.0839x; 1.0839x over previous
#include <cuda_runtime.h>
#include <cuda_bf16.h>

// Problem shape (fixed by dataset):
//   S = 8192  source codes
//   G = 1024  groups
//   T = 4096  time segments (t0 sorted ascending)
//   E = 16384 events
//
// out[t, g] = sum over events with start <= t0[t] < end of
//             rate[e] * weights[index[e]], grouped by group_id[index[e]].
//
// t0 sorted -> each event is two difference-array endpoints (+w at lo, -w at
// hi). Pipeline (3 launches, no zero kernel — consumers restore zeros):
//   1. bucket: binary search, push endpoint records per 8-row chunk +
//      atomic chunk-column sums into g_part[g][c].
//   2. scan:   warp-per-column shuffle scan of chunk sums -> exclusive
//      offsets written TRANSPOSED to g_off[c][g] (coalesced for apply);
//      zero-restores g_part; snapshots g_cnt -> g_cnt2 and resets g_cnt.
//   3. apply:  block = (chunk, group-half); rebuild 8x512 diff tile in smem
//      from records, prefix seeded by coalesced g_off read, write output.

#define T_DIM 4096
#define G_DIM 1024
#define G4    (G_DIM / 4)     // 256 float4 columns
#define CH    8               // rows per chunk
#define NCH   (T_DIM / CH)    // 512 chunks
#define CAP   512             // records per chunk (expected ~60, sigma ~8)

__device__ int   g_cnt[NCH];
__device__ int   g_cnt2[NCH];
__device__ uint2 g_rec[NCH][CAP];        // endpoint records, 2 MB
__device__ float g_part[G_DIM][NCH];     // chunk sums, column-contiguous, 2 MB
__device__ float g_off[NCH][G_DIM];      // exclusive offsets, chunk-major, 2 MB

// ---------------------------------------------------------------------------
// Kernel 1: per-event binary search -> endpoint records + chunk column sums
// ---------------------------------------------------------------------------
__device__ __forceinline__ void push_record(int row, int g, float w)
{
    int chunk = row >> 3;                // CH = 8
    int r     = row & (CH - 1);
    int pos = atomicAdd(&g_cnt[chunk], 1);
    if (pos < CAP) {
        g_rec[chunk][pos] = make_uint2((unsigned)((r << 10) | g),
                                       __float_as_uint(w));
        atomicAdd(&g_part[g][chunk], w);   // kept consistent with record
    }
}

__global__ void bucket_kernel(const int* __restrict__ index,
                              const float* __restrict__ rate,
                              const float* __restrict__ starttime,
                              const float* __restrict__ endtime,
                              const float* __restrict__ t0,
                              const int* __restrict__ group_id,
                              const float* __restrict__ weights,
                              int E)
{
    __shared__ float sh_t0[T_DIM];
    for (int i = threadIdx.x; i < T_DIM; i += blockDim.x)
        sh_t0[i] = t0[i];
    __syncthreads();

    int e = blockIdx.x * blockDim.x + threadIdx.x;
    if (e >= E) return;

    float st = starttime[e];
    float en = endtime[e];

    // lower_bound: first idx with t0[idx] >= x   (start <= t0 < end)
    int lo = 0, hi = T_DIM;
    while (lo < hi) {
        int m = (lo + hi) >> 1;
        if (sh_t0[m] < st) lo = m + 1; else hi = m;
    }
    int lo2 = lo, hi2 = T_DIM;
    while (lo2 < hi2) {
        int m = (lo2 + hi2) >> 1;
        if (sh_t0[m] < en) lo2 = m + 1; else hi2 = m;
    }
    if (lo >= lo2) return;

    int src = index[e];
    float w = rate[e] * weights[src];
    int g = group_id[src];

    push_record(lo, g, w);
    if (lo2 < T_DIM) push_record(lo2, g, -w);
}

// ---------------------------------------------------------------------------
// Kernel 2: exclusive scan of chunk sums per column; warp = one column.
// Block = 16 warps (16 columns), grid = 64. Results transposed through smem
// to g_off[c][g] (chunk-major, coalesced for apply). Restores g_part to 0,
// snapshots g_cnt -> g_cnt2 and resets g_cnt (so split apply blocks can
// read counts without a reset race).
// ---------------------------------------------------------------------------
__global__ void __launch_bounds__(512)
scan_kernel()
{
    __shared__ float sh[NCH][17];        // [c][warp], padded: ~34.8 KB
    int warp = threadIdx.x >> 5;
    int lane = threadIdx.x & 31;
    int g = blockIdx.x * 16 + warp;

    // lane owns chunks [lane*16, lane*16+16)
    float4* base = (float4*)&g_part[g][lane * 16];
    float v[16];
    #pragma unroll
    for (int q = 0; q < 4; q++) {
        float4 x = base[q];
        v[q*4+0] = x.x; v[q*4+1] = x.y; v[q*4+2] = x.z; v[q*4+3] = x.w;
    }
    // restore zeros for next replay
    float4 z = make_float4(0.f, 0.f, 0.f, 0.f);
    #pragma unroll
    for (int q = 0; q < 4; q++) base[q] = z;

    // per-lane total, then warp exclusive scan of totals
    float tot = 0.f;
    #pragma unroll
    for (int i = 0; i < 16; i++) tot += v[i];
    float excl = 0.f, acc = tot;
    #pragma unroll
    for (int off = 1; off < 32; off <<= 1) {
        float up = __shfl_up_sync(0xFFFFFFFFu, acc, off);
        if (lane >= off) acc += up;
    }
    excl = acc - tot;                    // exclusive prefix of lane totals

    // per-chunk exclusive prefixes into the transpose tile
    float run = excl;
    #pragma unroll
    for (int i = 0; i < 16; i++) {
        sh[lane * 16 + i][warp] = run;
        run += v[i];
    }

    // block 0 also snapshots + resets the record counts
    if (blockIdx.x == 0) {
        int c = threadIdx.x;             // 512 threads == NCH
        g_cnt2[c] = g_cnt[c];
        g_cnt[c] = 0;
    }
    __syncthreads();

    // write transposed: thread = row c, 16 contiguous floats (4x float4)
    int c = threadIdx.x;
    float4* dst = (float4*)&g_off[c][blockIdx.x * 16];
    #pragma unroll
    for (int q = 0; q < 4; q++)
        dst[q] = make_float4(sh[c][q*4+0], sh[c][q*4+1],
                             sh[c][q*4+2], sh[c][q*4+3]);
}

// ---------------------------------------------------------------------------
// Kernel 3: apply. Block = (chunk c, group-half h). Rebuild 8x512 diff tile
// in smem from this chunk's records (filtered by half), prefix seeded by a
// coalesced float4 offset read, write the output tile.
// ---------------------------------------------------------------------------
__global__ void __launch_bounds__(128)
apply_kernel(float4* __restrict__ out)
{
    __shared__ float4 sh[CH][128];       // 8 rows x 512 groups = 16 KB
    int b = blockIdx.x;
    int c = b >> 1;
    int h = b & 1;
    int t = threadIdx.x;                 // 0..127 float4 column within half

    int n = g_cnt2[c];
    if (n > CAP) n = CAP;

    float4 z = make_float4(0.f, 0.f, 0.f, 0.f);
    #pragma unroll
    for (int r = 0; r < CH; r++) sh[r][t] = z;
    __syncthreads();

    float* shf = (float*)sh;
    int gbase = h << 9;                  // h * 512
    for (int i = t; i < n; i += 128) {
        uint2 rec = g_rec[c][i];
        int g = rec.x & 1023;
        if ((g >> 9) == h) {
            int r = rec.x >> 10;
            atomicAdd(&shf[r * 512 + (g - gbase)], __uint_as_float(rec.y));
        }
    }
    __syncthreads();

    float4 run = *(const float4*)&g_off[c][gbase + 4 * t];
    float4* p = out + (size_t)c * CH * G4 + h * 128 + t;
    #pragma unroll
    for (int r = 0; r < CH; r++) {
        float4 v = sh[r][t];
        run.x += v.x; run.y += v.y; run.z += v.z; run.w += v.w;
        p[r * G4] = run;
    }
}

// ---------------------------------------------------------------------------
extern "C" void kernel_launch(void* const* d_in, const int* in_sizes, int n_in,
                              void* d_out, int out_size)
{
    const int*   index     = (const int*)  d_in[0];
    const float* rate      = (const float*)d_in[1];
    const float* starttime = (const float*)d_in[2];
    const float* endtime   = (const float*)d_in[3];
    const float* t0        = (const float*)d_in[4];
    const int*   group_id  = (const int*)  d_in[5];
    const float* weights   = (const float*)d_in[6];
    float*       out       = (float*)d_out;

    int E = in_sizes[0];

    int threads = 256;
    int blocks  = (E + threads - 1) / threads;
    bucket_kernel<<<blocks, threads>>>(index, rate, starttime, endtime,
                                       t0, group_id, weights, E);

    scan_kernel<<<G_DIM / 16, 512>>>();

    apply_kernel<<<NCH * 2, 128>>>((float4*)out);
}

// round 8
// speedup vs baseline: 1.0975x; 1.0125x over previous
#include <cuda_runtime.h>
#include <cuda_bf16.h>

// Problem shape (fixed by dataset):
//   S = 8192  source codes
//   G = 1024  groups
//   T = 4096  time segments (t0 sorted ascending)
//   E = 16384 events
//
// out[t, g] = sum over events with start <= t0[t] < end of
//             rate[e] * weights[index[e]], grouped by group_id[index[e]].
//
// t0 sorted -> each event is two difference-array endpoints (+w at lo, -w at
// hi). Pipeline (3 launches, consumers restore scratch zeros for replay):
//   1. bucket: ILP-2 bank-conflict-free binary search (XOR-swizzled shared
//      t0), push endpoint records per 8-row chunk + atomic chunk-column sums.
//   2. scan:   warp-per-column shuffle scan of chunk sums -> exclusive
//      offsets transposed to g_off[c][g]; zero-restores g_part; snapshots
//      g_cnt -> g_cnt2 and resets g_cnt.
//   3. apply:  block = (chunk, group-half); rebuild 8x512 diff tile in smem
//      from records, prefix seeded by coalesced g_off read, write output.

#define T_DIM 4096
#define G_DIM 1024
#define G4    (G_DIM / 4)     // 256 float4 columns
#define CH    8               // rows per chunk
#define NCH   (T_DIM / CH)    // 512 chunks
#define CAP   512             // records per chunk (expected ~60, sigma ~8)

// Bank-conflict-breaking bijection on [0, 4096): x ^ (x>>5) ^ (x>>10).
// Linear over GF(2), invertible (inverse = x ^ (x>>5)); any power-of-2
// probe stride >= 32 perturbs the low 5 bits -> distinct banks.
#define SWZ(m) ((m) ^ ((m) >> 5) ^ ((m) >> 10))

__device__ int   g_cnt[NCH];
__device__ int   g_cnt2[NCH];
__device__ uint2 g_rec[NCH][CAP];        // endpoint records, 2 MB
__device__ float g_part[G_DIM][NCH];     // chunk sums, column-contiguous, 2 MB
__device__ float g_off[NCH][G_DIM];      // exclusive offsets, chunk-major, 2 MB

// ---------------------------------------------------------------------------
// Kernel 1: per-event binary search -> endpoint records + chunk column sums
// ---------------------------------------------------------------------------
__device__ __forceinline__ void push_record(int row, int g, float w)
{
    int chunk = row >> 3;                // CH = 8
    int r     = row & (CH - 1);
    int pos = atomicAdd(&g_cnt[chunk], 1);
    if (pos < CAP) {
        atomicAdd(&g_part[g][chunk], w); // kept consistent with record
        g_rec[chunk][pos] = make_uint2((unsigned)((r << 10) | g),
                                       __float_as_uint(w));
    }
}

__global__ void __launch_bounds__(128)
bucket_kernel(const int* __restrict__ index,
              const float* __restrict__ rate,
              const float* __restrict__ starttime,
              const float* __restrict__ endtime,
              const float* __restrict__ t0,
              const int* __restrict__ group_id,
              const float* __restrict__ weights,
              int E)
{
    __shared__ float sh_t0[T_DIM];
    for (int i = threadIdx.x; i < T_DIM; i += 128)
        sh_t0[SWZ(i)] = t0[i];

    int e = blockIdx.x * 128 + threadIdx.x;
    // Prefetch event data before the search (overlaps the LDS chain)
    float st = 0.f, en = 0.f, rt = 0.f, wgt = 0.f;
    int src = 0, g = 0;
    bool valid = (e < E);
    if (valid) {
        st  = starttime[e];
        en  = endtime[e];
        rt  = rate[e];
        src = index[e];
    }
    if (valid) {                          // dependent loads, still pre-search
        wgt = weights[src];
        g   = group_id[src];
    }
    __syncthreads();

    if (!valid) return;

    // Two INDEPENDENT lower_bound searches (first idx with t0[idx] >= x),
    // fully unrolled: 2^12 = 4096, exactly 12 levels. ILP-2 LDS chains.
    int lo = 0, hi = T_DIM, lo2 = 0, hi2 = T_DIM;
    #pragma unroll
    for (int it = 0; it < 12; it++) {
        int m1 = (lo + hi) >> 1;
        int m2 = (lo2 + hi2) >> 1;
        float a = sh_t0[SWZ(m1)];
        float b = sh_t0[SWZ(m2)];
        if (a < st) lo = m1 + 1; else hi = m1;
        if (b < en) lo2 = m2 + 1; else hi2 = m2;
    }
    // active range is [lo, lo2)
    if (lo >= lo2) return;

    float w = rt * wgt;
    push_record(lo, g, w);
    if (lo2 < T_DIM) push_record(lo2, g, -w);
}

// ---------------------------------------------------------------------------
// Kernel 2: exclusive scan of chunk sums per column; warp = one column.
// Block = 16 warps (16 columns), grid = 64. Results transposed through smem
// to g_off[c][g] (chunk-major, coalesced for apply). Restores g_part to 0,
// snapshots g_cnt -> g_cnt2 and resets g_cnt.
// ---------------------------------------------------------------------------
__global__ void __launch_bounds__(512)
scan_kernel()
{
    __shared__ float sh[NCH][17];        // [c][warp], padded
    int warp = threadIdx.x >> 5;
    int lane = threadIdx.x & 31;
    int g = blockIdx.x * 16 + warp;

    // lane owns chunks [lane*16, lane*16+16)
    float4* base = (float4*)&g_part[g][lane * 16];
    float v[16];
    #pragma unroll
    for (int q = 0; q < 4; q++) {
        float4 x = base[q];
        v[q*4+0] = x.x; v[q*4+1] = x.y; v[q*4+2] = x.z; v[q*4+3] = x.w;
    }
    // restore zeros for next replay
    float4 z = make_float4(0.f, 0.f, 0.f, 0.f);
    #pragma unroll
    for (int q = 0; q < 4; q++) base[q] = z;

    // per-lane total, then warp exclusive scan of totals
    float tot = 0.f;
    #pragma unroll
    for (int i = 0; i < 16; i++) tot += v[i];
    float acc = tot;
    #pragma unroll
    for (int off = 1; off < 32; off <<= 1) {
        float up = __shfl_up_sync(0xFFFFFFFFu, acc, off);
        if (lane >= off) acc += up;
    }
    float excl = acc - tot;              // exclusive prefix of lane totals

    // per-chunk exclusive prefixes into the transpose tile
    float run = excl;
    #pragma unroll
    for (int i = 0; i < 16; i++) {
        sh[lane * 16 + i][warp] = run;
        run += v[i];
    }

    // block 0 also snapshots + resets the record counts
    if (blockIdx.x == 0) {
        int c = threadIdx.x;             // 512 threads == NCH
        g_cnt2[c] = g_cnt[c];
        g_cnt[c] = 0;
    }
    __syncthreads();

    // write transposed: thread = row c, 16 contiguous floats (4x float4)
    int c = threadIdx.x;
    float4* dst = (float4*)&g_off[c][blockIdx.x * 16];
    #pragma unroll
    for (int q = 0; q < 4; q++)
        dst[q] = make_float4(sh[c][q*4+0], sh[c][q*4+1],
                             sh[c][q*4+2], sh[c][q*4+3]);
}

// ---------------------------------------------------------------------------
// Kernel 3: apply. Block = (chunk c, group-half h). Rebuild 8x512 diff tile
// in smem from this chunk's records (filtered by half), prefix seeded by a
// coalesced float4 offset read, write the output tile.
// ---------------------------------------------------------------------------
__global__ void __launch_bounds__(128)
apply_kernel(float4* __restrict__ out)
{
    __shared__ float4 sh[CH][128];       // 8 rows x 512 groups = 16 KB
    int b = blockIdx.x;
    int c = b >> 1;
    int h = b & 1;
    int t = threadIdx.x;                 // 0..127 float4 column within half

    int n = g_cnt2[c];
    if (n > CAP) n = CAP;

    float4 z = make_float4(0.f, 0.f, 0.f, 0.f);
    #pragma unroll
    for (int r = 0; r < CH; r++) sh[r][t] = z;
    __syncthreads();

    float* shf = (float*)sh;
    int gbase = h << 9;                  // h * 512
    for (int i = t; i < n; i += 128) {
        uint2 rec = g_rec[c][i];
        int g = rec.x & 1023;
        if ((g >> 9) == h) {
            int r = rec.x >> 10;
            atomicAdd(&shf[r * 512 + (g - gbase)], __uint_as_float(rec.y));
        }
    }
    __syncthreads();

    float4 run = *(const float4*)&g_off[c][gbase + 4 * t];
    float4* p = out + (size_t)c * CH * G4 + h * 128 + t;
    #pragma unroll
    for (int r = 0; r < CH; r++) {
        float4 v = sh[r][t];
        run.x += v.x; run.y += v.y; run.z += v.z; run.w += v.w;
        p[r * G4] = run;
    }
}

// ---------------------------------------------------------------------------
extern "C" void kernel_launch(void* const* d_in, const int* in_sizes, int n_in,
                              void* d_out, int out_size)
{
    const int*   index     = (const int*)  d_in[0];
    const float* rate      = (const float*)d_in[1];
    const float* starttime = (const float*)d_in[2];
    const float* endtime   = (const float*)d_in[3];
    const float* t0        = (const float*)d_in[4];
    const int*   group_id  = (const int*)  d_in[5];
    const float* weights   = (const float*)d_in[6];

    int E = in_sizes[0];

    bucket_kernel<<<(E + 127) / 128, 128>>>(index, rate, starttime, endtime,
                                            t0, group_id, weights, E);

    scan_kernel<<<G_DIM / 16, 512>>>();

    apply_kernel<<<NCH * 2, 128>>>((float4*)d_out);
}